// round 14
// baseline (speedup 1.0000x reference)
#include <cuda_runtime.h>
#include <math_constants.h>
#include <cstdint>

#define H 1024
#define V 50257
#define L 12
#define TILES ((V + 7) / 8)          // 6283 projection tiles, 8 rows each
#define NA1 128                      // attn+comb blocks
#define NA2 512                      // hh blocks
#define NA  (NA1 + NA2)              // 640
#define GRID_MEGA (NA + TILES)       // 6923

// ---- device scratch (no allocations allowed), 16B-aligned ----
__device__ __align__(16) float g_x[H];         // relu(combine) output
__device__ __align__(16) float g_h[H];         // h_new (aligned copy)
__device__ __align__(16) float g_hh[4 * H];    // W_hh@h0 + b_ih + b_hh
__device__ float g_sum;                        // sum(exp(logit)) accumulator
__device__ unsigned c_gx, c_hh, c_h;           // progress counters (k4 resets)

__device__ __forceinline__ float warp_sum(float v) {
#pragma unroll
    for (int o = 16; o; o >>= 1) v += __shfl_xor_sync(0xffffffffu, v, o);
    return v;
}

__device__ __forceinline__ float4 ldcs4(const float4* p) { return __ldcs(p); }

__device__ __forceinline__ unsigned ld_acq(const unsigned* p) {
    unsigned v;
    asm volatile("ld.global.acquire.gpu.u32 %0, [%1];" : "=r"(v) : "l"(p) : "memory");
    return v;
}

__device__ __forceinline__ void cp16(unsigned int saddr, const void* gptr) {
    asm volatile("cp.async.cg.shared.global [%0], [%1], 16;" :: "r"(saddr), "l"(gptr));
}

// ============================================================
// MEGA kernel: everything except the final subtract.
//  bid 0..127    (A1): attn + combine -> g_x ; then ih gates + cell -> g_h
//  bid 128..639  (A2): hh gate rows -> g_hh
//  bid 640..6922 (B) : prefetch 8 out_W rows to smem via cp.async,
//                      wait for g_h, dot from smem, logits + REDG sum.
// ============================================================
__global__ void __launch_bounds__(256, 5)
mega(const int* input,
     const float* __restrict__ h_hidden,
     const float* __restrict__ c_hidden,
     const float* __restrict__ enc,
     const float* __restrict__ emb,
     const float* __restrict__ attn_W,
     const float* __restrict__ attn_b,
     const float* __restrict__ comb_W,
     const float* __restrict__ comb_b,
     const float* __restrict__ W_ih,
     const float* __restrict__ W_hh,
     const float* __restrict__ b_ih,
     const float* __restrict__ b_hh,
     const float* __restrict__ out_W,
     const float* __restrict__ out_b,
     float* __restrict__ logits,
     float* __restrict__ h_new,
     float* __restrict__ c_new,
     float* __restrict__ attnw_out) {
    __shared__ __align__(16) char s_raw[36864];   // 36 KB workspace
    __shared__ float s_small[32];
    __shared__ int s_go;
    const int tid = threadIdx.x;
    const int w = tid >> 5, lane = tid & 31;
    const int bid = blockIdx.x;

    if (bid < NA1) {
        // ================= A1: attention + combine =================
        float* s_in = (float*)s_raw;              // 2H floats
        float* s_cx = (float*)(s_raw + 8192);     // 2H floats
        float* s_logit = s_small;                 // L
        float* s_w = s_small + 16;                // L

        if (bid == 0 && tid == 0) g_sum = 0.f;    // before any B adds (via c_h chain)

        const int idx = input[0];                 // low 32 bits of LE int64
        const float* e = emb + (size_t)idx * H;
        for (int i = tid; i < H; i += 256) {
            float v = e[i];
            s_in[i] = v;
            s_cx[i] = v;
            s_in[H + i] = h_hidden[i];
        }
        __syncthreads();

        const float4* s_in4 = (const float4*)s_in;
        for (int l = w; l < L; l += 8) {
            const float4* row = (const float4*)(attn_W + (size_t)l * 2 * H);
            float acc = 0.f;
#pragma unroll
            for (int t = 0; t < 16; t++) {
                float4 a = row[lane + 32 * t];
                float4 b = s_in4[lane + 32 * t];
                acc += a.x * b.x + a.y * b.y + a.z * b.z + a.w * b.w;
            }
            acc = warp_sum(acc);
            if (lane == 0) s_logit[l] = acc + attn_b[l];
        }
        __syncthreads();

        if (tid == 0) {
            float m = -1e30f;
#pragma unroll
            for (int l = 0; l < L; l++) m = fmaxf(m, s_logit[l]);
            float s = 0.f;
#pragma unroll
            for (int l = 0; l < L; l++) { float ex = expf(s_logit[l] - m); s_w[l] = ex; s += ex; }
            float inv = 1.f / s;
#pragma unroll
            for (int l = 0; l < L; l++) s_w[l] *= inv;
            if (bid == 0)
#pragma unroll
                for (int l = 0; l < L; l++) attnw_out[l] = s_w[l];
        }
        __syncthreads();

        for (int j = tid; j < H; j += 256) {
            float acc = 0.f;
#pragma unroll
            for (int l = 0; l < L; l++) acc += s_w[l] * enc[l * H + j];
            s_cx[H + j] = acc;
        }
        __syncthreads();

        {
            const int r = bid * 8 + w;
            const float4* s_cx4 = (const float4*)s_cx;
            const float4* row = (const float4*)(comb_W + (size_t)r * 2 * H);
            float acc = 0.f;
#pragma unroll
            for (int t = 0; t < 16; t++) {
                float4 a = ldcs4(row + lane + 32 * t);
                float4 b = s_cx4[lane + 32 * t];
                acc += a.x * b.x + a.y * b.y + a.z * b.z + a.w * b.w;
            }
            acc = warp_sum(acc);
            if (lane == 0) g_x[r] = fmaxf(acc + comb_b[r], 0.f);
        }
        __threadfence();                           // release g_x stores
        __syncthreads();
        if (tid == 0) atomicAdd(&c_gx, 1u);

        // ---- wait for all g_x (A1) and all g_hh (A2) ----
        for (;;) {
            if (tid == 0)
                s_go = (ld_acq(&c_gx) == NA1 && ld_acq(&c_hh) == NA2);
            __syncthreads();
            if (s_go) break;
            if (tid == 0) __nanosleep(128);
            __syncthreads();
        }

        // ================= A1 phase 2: ih gates + cell =================
        float4* s_x = (float4*)s_raw;
        s_x[tid] = ((const float4*)g_x)[tid];
        __syncthreads();

        const int j = bid * 8 + w;                // hidden unit, warp-per-unit
        float gate[4];
#pragma unroll
        for (int gp = 0; gp < 2; gp++) {
            const float4* r0 = (const float4*)(W_ih + (size_t)((2 * gp) * H + j) * H);
            const float4* r1 = (const float4*)(W_ih + (size_t)((2 * gp + 1) * H + j) * H);
            float a0 = 0.f, a1 = 0.f;
#pragma unroll
            for (int t = 0; t < 8; t++) {
                float4 w0 = ldcs4(r0 + lane + 32 * t);
                float4 w1 = ldcs4(r1 + lane + 32 * t);
                float4 xb = s_x[lane + 32 * t];
                a0 += w0.x * xb.x + w0.y * xb.y + w0.z * xb.z + w0.w * xb.w;
                a1 += w1.x * xb.x + w1.y * xb.y + w1.z * xb.z + w1.w * xb.w;
            }
            gate[2 * gp]     = warp_sum(a0);
            gate[2 * gp + 1] = warp_sum(a1);
        }
        if (lane == 0) {
            float gi = gate[0] + g_hh[j];
            float gf = gate[1] + g_hh[H + j];
            float gg = gate[2] + g_hh[2 * H + j];
            float go = gate[3] + g_hh[3 * H + j];
            float si = 1.f / (1.f + expf(-gi));
            float sf = 1.f / (1.f + expf(-gf));
            float so = 1.f / (1.f + expf(-go));
            float c = sf * c_hidden[j] + si * tanhf(gg);
            float h = so * tanhf(c);
            c_new[j] = c;
            h_new[j] = h;
            g_h[j] = h;
        }
        __threadfence();                           // release g_h stores
        __syncthreads();
        if (tid == 0) atomicAdd(&c_h, 1u);
        return;
    }

    if (bid < NA) {
        // ================= A2: hh gate rows =================
        float4* s_v = (float4*)s_raw;
        s_v[tid] = ((const float4*)h_hidden)[tid];
        __syncthreads();
        const int r = (bid - NA1) * 8 + w;         // [0, 4096)
        const float4* row = (const float4*)(W_hh + (size_t)r * H);
        float acc = 0.f;
#pragma unroll
        for (int t = 0; t < 8; t++) {
            float4 a = ldcs4(row + lane + 32 * t);
            float4 b = s_v[lane + 32 * t];
            acc += a.x * b.x + a.y * b.y + a.z * b.z + a.w * b.w;
        }
        acc = warp_sum(acc);
        if (lane == 0) g_hh[r] = acc + b_ih[r] + b_hh[r];
        __threadfence();                           // release g_hh stores
        __syncthreads();
        if (tid == 0) atomicAdd(&c_hh, 1u);
        return;
    }

    // ================= B: projection tile =================
    const int t = bid - NA;                        // tile index [0, TILES)
    float4* s_w4 = (float4*)s_raw;                 // 2048 float4 = 32 KB
    float4* s_h4 = (float4*)(s_raw + 32768);       // 256 float4 = 4 KB

    // prefetch 8 rows of out_W into smem NOW (independent of g_h)
    {
        unsigned int sbase = (unsigned int)__cvta_generic_to_shared(s_w4);
#pragma unroll
        for (int i = 0; i < 8; i++) {
            int idx = tid + i * 256;               // [0, 2048)
            int row = idx >> 8;                    // 0..7
            if (t * 8 + row < V)
                cp16(sbase + idx * 16,
                     out_W + (size_t)(t * 8 + row) * H + (idx & 255) * 4);
        }
        asm volatile("cp.async.commit_group;");
    }

    // wait for h (usually already ready for non-wave-1 blocks)
    for (;;) {
        if (tid == 0) s_go = (ld_acq(&c_h) == NA1);
        __syncthreads();
        if (s_go) break;
        if (tid == 0) __nanosleep(128);
        __syncthreads();
    }
    s_h4[tid] = ((const float4*)g_h)[tid];
    asm volatile("cp.async.wait_group 0;" ::: "memory");
    __syncthreads();

    const int r = t * 8 + w;
    float l = -CUDART_INF_F;
    if (r < V) {
        float acc = 0.f;
#pragma unroll
        for (int q = 0; q < 8; q++) {
            float4 a = s_w4[w * 256 + lane + 32 * q];
            float4 b = s_h4[lane + 32 * q];
            acc += a.x * b.x + a.y * b.y + a.z * b.z + a.w * b.w;
        }
        acc = warp_sum(acc);
        if (lane == 0) {
            l = acc + out_b[r];
            logits[r] = l;
        }
    }
    if (lane == 0) s_small[w] = l;
    __syncthreads();
    if (tid == 0) {
        float s = 0.f;
#pragma unroll
        for (int i = 0; i < 8; i++) {
            float v = s_small[i];
            if (v != -CUDART_INF_F) s += expf(v);
        }
        atomicAdd(&g_sum, s);                      // REDG: fire-and-forget
    }
}

// ============================================================
// k4: logp[i] = logits[i] - log(g_sum); resets counters for the
// next graph replay (stream-ordered after mega).
// ============================================================
__global__ void k4_sub(float* __restrict__ logp) {
    __shared__ float s_lse;
    const int tid = threadIdx.x;
    if (blockIdx.x == 0 && tid == 0) { c_gx = 0; c_hh = 0; c_h = 0; }
    if (tid == 0) s_lse = logf(g_sum);
    __syncthreads();
    const float lse = s_lse;
    const int i = blockIdx.x * 256 + tid;
    if (i < V) logp[i] -= lse;
}

// ============================================================
extern "C" void kernel_launch(void* const* d_in, const int* in_sizes, int n_in,
                              void* d_out, int out_size) {
    const int*   input   = (const int*)  d_in[0];
    const float* h_hid   = (const float*)d_in[1];
    const float* c_hid   = (const float*)d_in[2];
    const float* enc     = (const float*)d_in[3];
    const float* emb     = (const float*)d_in[4];
    const float* attn_W  = (const float*)d_in[5];
    const float* attn_b  = (const float*)d_in[6];
    const float* comb_W  = (const float*)d_in[7];
    const float* comb_b  = (const float*)d_in[8];
    const float* W_ih    = (const float*)d_in[9];
    const float* W_hh    = (const float*)d_in[10];
    const float* b_ih    = (const float*)d_in[11];
    const float* b_hh    = (const float*)d_in[12];
    const float* out_W   = (const float*)d_in[13];
    const float* out_b   = (const float*)d_in[14];

    float* out   = (float*)d_out;
    float* logp  = out;                 // [V]
    float* h_new = out + V;             // [H]
    float* c_new = out + V + H;         // [H]
    float* attnw = out + V + 2 * H;     // [L]

    mega<<<GRID_MEGA, 256>>>(input, h_hid, c_hid, enc, emb, attn_W, attn_b,
                             comb_W, comb_b, W_ih, W_hh, b_ih, b_hh,
                             out_W, out_b, logp, h_new, c_new, attnw);
    k4_sub<<<(V + 255) / 256, 256>>>(logp);
}

// round 15
// speedup vs baseline: 1.4664x; 1.4664x over previous
#include <cuda_runtime.h>
#include <math_constants.h>
#include <cstdint>

#define H 1024
#define V 50257
#define L 12
#define TILES ((V + 7) / 8)          // 6283 blocks in k3, 8 rows each

// ---- device scratch (no allocations allowed), 16B-aligned ----
__device__ __align__(16) float g_x[H];         // relu(combine) output
__device__ __align__(16) float g_h[H];         // h_new (aligned copy)
__device__ __align__(16) float g_hh[4 * H];    // W_hh@h0 + b_ih + b_hh
__device__ float g_sum;                        // global sum(exp(logit)) accumulator

__device__ __forceinline__ float warp_sum(float v) {
#pragma unroll
    for (int o = 16; o; o >>= 1) v += __shfl_xor_sync(0xffffffffu, v, o);
    return v;
}

__device__ __forceinline__ float4 ldcs4(const float4* p) { return __ldcs(p); }

// PDL controls (sm_90+): trigger lets the NEXT grid start launching;
// wait blocks until the PREVIOUS grid fully completed (memory visible).
__device__ __forceinline__ void pdl_trigger() {
#if __CUDA_ARCH__ >= 900
    asm volatile("griddepcontrol.launch_dependents;");
#endif
}
__device__ __forceinline__ void pdl_wait() {
#if __CUDA_ARCH__ >= 900
    asm volatile("griddepcontrol.wait;" ::: "memory");
#endif
}
__device__ __forceinline__ void l2_prefetch(const void* p) {
    asm volatile("prefetch.global.L2 [%0];" :: "l"(p));
}

// ============================================================
// Kernel 1:
//   blocks 0..127   : attention + combine (8 rows each)
//   blocks 128..639 : hh gate half: g_hh[r] = W_hh[r]@h0 + b_ih[r] + b_hh[r]
// Triggers dependents at entry so k2/k3 can begin prefetching.
// ============================================================
__global__ void k1_attn_comb_hh(const int* input,
                                const float* __restrict__ h_hidden,
                                const float* __restrict__ enc,
                                const float* __restrict__ emb,
                                const float* __restrict__ attn_W,
                                const float* __restrict__ attn_b,
                                const float* __restrict__ comb_W,
                                const float* __restrict__ comb_b,
                                const float* __restrict__ W_hh,
                                const float* __restrict__ b_ih,
                                const float* __restrict__ b_hh,
                                float* __restrict__ attnw_out) {
    const int tid = threadIdx.x;
    const int w = tid >> 5, lane = tid & 31;
    pdl_trigger();

    if (blockIdx.x >= 128) {
        __shared__ __align__(16) float4 s_h[256];
        s_h[tid] = ((const float4*)h_hidden)[tid];
        __syncthreads();
        const int r = (blockIdx.x - 128) * 8 + w;      // [0, 4096)
        const float4* row = (const float4*)(W_hh + (size_t)r * H);
        float acc = 0.f;
#pragma unroll
        for (int t = 0; t < 8; t++) {
            float4 a = ldcs4(row + lane + 32 * t);
            float4 b = s_h[lane + 32 * t];
            acc += a.x * b.x + a.y * b.y + a.z * b.z + a.w * b.w;
        }
        acc = warp_sum(acc);
        if (lane == 0) g_hh[r] = acc + b_ih[r] + b_hh[r];
        return;
    }

    __shared__ __align__(16) float s_in[2 * H];   // [emb ; h0]
    __shared__ __align__(16) float s_cx[2 * H];   // [emb ; applied]
    __shared__ float s_logit[L];
    __shared__ float s_w[L];

    if (blockIdx.x == 0 && tid == 0) g_sum = 0.f;  // reset accumulator per replay

    const int idx = input[0];     // low 32 bits of LE int64 index
    const float* e = emb + (size_t)idx * H;
    for (int i = tid; i < H; i += 256) {
        float v = e[i];
        s_in[i] = v;
        s_cx[i] = v;
        s_in[H + i] = h_hidden[i];
    }
    __syncthreads();

    const float4* s_in4 = (const float4*)s_in;
    for (int l = w; l < L; l += 8) {
        const float4* row = (const float4*)(attn_W + (size_t)l * 2 * H);
        float acc = 0.f;
#pragma unroll
        for (int t = 0; t < 16; t++) {
            float4 a = row[lane + 32 * t];
            float4 b = s_in4[lane + 32 * t];
            acc += a.x * b.x + a.y * b.y + a.z * b.z + a.w * b.w;
        }
        acc = warp_sum(acc);
        if (lane == 0) s_logit[l] = acc + attn_b[l];
    }
    __syncthreads();

    if (tid == 0) {
        float m = -1e30f;
#pragma unroll
        for (int l = 0; l < L; l++) m = fmaxf(m, s_logit[l]);
        float s = 0.f;
#pragma unroll
        for (int l = 0; l < L; l++) { float ex = expf(s_logit[l] - m); s_w[l] = ex; s += ex; }
        float inv = 1.f / s;
#pragma unroll
        for (int l = 0; l < L; l++) s_w[l] *= inv;
        if (blockIdx.x == 0)
#pragma unroll
            for (int l = 0; l < L; l++) attnw_out[l] = s_w[l];
    }
    __syncthreads();

    for (int j = tid; j < H; j += 256) {
        float acc = 0.f;
#pragma unroll
        for (int l = 0; l < L; l++) acc += s_w[l] * enc[l * H + j];
        s_cx[H + j] = acc;
    }
    __syncthreads();

    const int r = blockIdx.x * 8 + w;
    const float4* s_cx4 = (const float4*)s_cx;
    const float4* row = (const float4*)(comb_W + (size_t)r * 2 * H);
    float acc = 0.f;
#pragma unroll
    for (int t = 0; t < 16; t++) {
        float4 a = ldcs4(row + lane + 32 * t);
        float4 b = s_cx4[lane + 32 * t];
        acc += a.x * b.x + a.y * b.y + a.z * b.z + a.w * b.w;
    }
    acc = warp_sum(acc);
    if (lane == 0) g_x[r] = fmaxf(acc + comb_b[r], 0.f);
}

// ============================================================
// Kernel 2: ih-half of gates + LSTM cell, fused. PDL consumer:
// prefetches its 4 W_ih rows into L2 BEFORE waiting on k1.
// ============================================================
__global__ void k2_gates_cell(const float* __restrict__ c_hidden,
                              const float* __restrict__ W_ih,
                              float* __restrict__ h_new,
                              float* __restrict__ c_new) {
    __shared__ __align__(16) float4 s_x[256];
    const int tid = threadIdx.x;
    const int w = tid >> 5, lane = tid & 31;
    const int j = blockIdx.x * 8 + w;
    pdl_trigger();

    // pre-wait L2 prefetch of this block's W_ih rows (constant data)
#pragma unroll
    for (int g = 0; g < 4; g++) {
        const char* base = (const char*)(W_ih + (size_t)(g * H + j) * H);
#pragma unroll
        for (int q = 0; q < 1; q++)     // 32 lanes x 128B = full 4KB row
            l2_prefetch(base + lane * 128);
    }

    pdl_wait();                          // k1's g_x / g_hh now visible
    s_x[tid] = ((const float4*)g_x)[tid];
    __syncthreads();

    float gate[4];
#pragma unroll
    for (int gp = 0; gp < 2; gp++) {
        const float4* r0 = (const float4*)(W_ih + (size_t)((2 * gp) * H + j) * H);
        const float4* r1 = (const float4*)(W_ih + (size_t)((2 * gp + 1) * H + j) * H);
        float a0 = 0.f, a1 = 0.f;
#pragma unroll
        for (int t = 0; t < 8; t++) {
            float4 w0 = ldcs4(r0 + lane + 32 * t);
            float4 w1 = ldcs4(r1 + lane + 32 * t);
            float4 xb = s_x[lane + 32 * t];
            a0 += w0.x * xb.x + w0.y * xb.y + w0.z * xb.z + w0.w * xb.w;
            a1 += w1.x * xb.x + w1.y * xb.y + w1.z * xb.z + w1.w * xb.w;
        }
        gate[2 * gp]     = warp_sum(a0);
        gate[2 * gp + 1] = warp_sum(a1);
    }
    if (lane == 0) {
        float gi = gate[0] + g_hh[j];
        float gf = gate[1] + g_hh[H + j];
        float gg = gate[2] + g_hh[2 * H + j];
        float go = gate[3] + g_hh[3 * H + j];
        float si = 1.f / (1.f + expf(-gi));
        float sf = 1.f / (1.f + expf(-gf));
        float so = 1.f / (1.f + expf(-go));
        float c = sf * c_hidden[j] + si * tanhf(gg);
        float h = so * tanhf(c);
        c_new[j] = c;
        h_new[j] = h;
        g_h[j] = h;
    }
}

// ============================================================
// Kernel 3: output projection, 8 rows/block, warp-per-row.
// PDL consumer: prefetches its 32KB out_W tile into L2 BEFORE
// waiting. Epilogue: fire-and-forget REDG into g_sum.
// ============================================================
__global__ void k3_out(const float* __restrict__ out_W,
                       const float* __restrict__ out_b,
                       float* __restrict__ logits) {
    __shared__ __align__(16) float4 s_h[256];
    __shared__ float s_l[8];
    const int tid = threadIdx.x;
    const int w = tid >> 5, lane = tid & 31;
    const int r = blockIdx.x * 8 + w;
    pdl_trigger();

    // pre-wait L2 prefetch: 8 rows x 4KB = 32KB, 256 threads x 128B line
    if (r < V) {
        const char* base = (const char*)(out_W + (size_t)r * H);
        l2_prefetch(base + lane * 128);  // 32 lanes cover the 4KB row
    }

    pdl_wait();                          // k2's g_h now visible
    s_h[tid] = ((const float4*)g_h)[tid];
    __syncthreads();

    float l = -CUDART_INF_F;
    if (r < V) {
        const float4* row = (const float4*)(out_W + (size_t)r * H);
        float acc = 0.f;
#pragma unroll
        for (int t = 0; t < 8; t++) {
            float4 a = ldcs4(row + lane + 32 * t);
            float4 b = s_h[lane + 32 * t];
            acc += a.x * b.x + a.y * b.y + a.z * b.z + a.w * b.w;
        }
        acc = warp_sum(acc);
        if (lane == 0) {
            l = acc + out_b[r];
            logits[r] = l;
        }
    }
    if (lane == 0) s_l[w] = l;
    __syncthreads();
    if (tid == 0) {
        float s = 0.f;
#pragma unroll
        for (int i = 0; i < 8; i++) {
            float v = s_l[i];
            if (v != -CUDART_INF_F) s += expf(v);
        }
        atomicAdd(&g_sum, s);            // REDG: no return value, no fence
    }
}

// ============================================================
// Kernel 4: logp[i] = logits[i] - log(g_sum). PDL consumer.
// ============================================================
__global__ void k4_sub(float* __restrict__ logp) {
    __shared__ float s_lse;
    const int tid = threadIdx.x;
    pdl_wait();
    if (tid == 0) s_lse = logf(g_sum);
    __syncthreads();
    const float lse = s_lse;
    const int i = blockIdx.x * 256 + tid;
    if (i < V) logp[i] -= lse;
}

// ============================================================
static inline void launch_pdl(void* fn, dim3 grid, dim3 block, void** args) {
    cudaLaunchAttribute attr[1];
    attr[0].id = cudaLaunchAttributeProgrammaticStreamSerialization;
    attr[0].val.programmaticStreamSerializationAllowed = 1;
    cudaLaunchConfig_t cfg = {};
    cfg.gridDim = grid;
    cfg.blockDim = block;
    cfg.dynamicSmemBytes = 0;
    cfg.stream = 0;
    cfg.attrs = attr;
    cfg.numAttrs = 1;
    cudaLaunchKernelExC(&cfg, fn, args);
}

extern "C" void kernel_launch(void* const* d_in, const int* in_sizes, int n_in,
                              void* d_out, int out_size) {
    const int*   input   = (const int*)  d_in[0];
    const float* h_hid   = (const float*)d_in[1];
    const float* c_hid   = (const float*)d_in[2];
    const float* enc     = (const float*)d_in[3];
    const float* emb     = (const float*)d_in[4];
    const float* attn_W  = (const float*)d_in[5];
    const float* attn_b  = (const float*)d_in[6];
    const float* comb_W  = (const float*)d_in[7];
    const float* comb_b  = (const float*)d_in[8];
    const float* W_ih    = (const float*)d_in[9];
    const float* W_hh    = (const float*)d_in[10];
    const float* b_ih    = (const float*)d_in[11];
    const float* b_hh    = (const float*)d_in[12];
    const float* out_W   = (const float*)d_in[13];
    const float* out_b   = (const float*)d_in[14];

    float* out   = (float*)d_out;
    float* logp  = out;                 // [V]
    float* h_new = out + V;             // [H]
    float* c_new = out + V + H;         // [H]
    float* attnw = out + V + 2 * H;     // [L]

    k1_attn_comb_hh<<<128 + 512, 256>>>(input, h_hid, enc, emb, attn_W, attn_b,
                                        comb_W, comb_b, W_hh, b_ih, b_hh, attnw);
    {
        void* args[] = { (void*)&c_hid, (void*)&W_ih, (void*)&h_new, (void*)&c_new };
        launch_pdl((void*)k2_gates_cell, dim3(128), dim3(256), args);
    }
    {
        void* args[] = { (void*)&out_W, (void*)&out_b, (void*)&logp };
        launch_pdl((void*)k3_out, dim3(TILES), dim3(256), args);
    }
    {
        void* args[] = { (void*)&logp };
        launch_pdl((void*)k4_sub, dim3((V + 255) / 256), dim3(256), args);
    }
}

// round 16
// speedup vs baseline: 1.5777x; 1.0759x over previous
#include <cuda_runtime.h>
#include <math_constants.h>
#include <cstdint>

#define H 1024
#define V 50257
#define L 12
#define TILES ((V + 7) / 8)          // 6283 blocks in k3, 8 rows each

// ---- device scratch (no allocations allowed), 16B-aligned ----
__device__ __align__(16) float g_x[H];         // relu(combine) output
__device__ __align__(16) float g_h[H];         // h_new (aligned copy)
__device__ float g_sum;                        // global sum(exp(logit)) accumulator

__device__ __forceinline__ float warp_sum(float v) {
#pragma unroll
    for (int o = 16; o; o >>= 1) v += __shfl_xor_sync(0xffffffffu, v, o);
    return v;
}

__device__ __forceinline__ float4 ldcs4(const float4* p) { return __ldcs(p); }

// PDL controls (sm_90+)
__device__ __forceinline__ void pdl_trigger() {
#if __CUDA_ARCH__ >= 900
    asm volatile("griddepcontrol.launch_dependents;");
#endif
}
__device__ __forceinline__ void pdl_wait() {
#if __CUDA_ARCH__ >= 900
    asm volatile("griddepcontrol.wait;" ::: "memory");
#endif
}
__device__ __forceinline__ void l2_prefetch(const void* p) {
    asm volatile("prefetch.global.L2 [%0];" :: "l"(p));
}

// ============================================================
// Kernel 1: attention (redundant per block) + combine only.
// 128 blocks x 256 threads. Triggers dependents at entry.
// ============================================================
__global__ void k1_attn_comb(const int* input,
                             const float* __restrict__ h_hidden,
                             const float* __restrict__ enc,
                             const float* __restrict__ emb,
                             const float* __restrict__ attn_W,
                             const float* __restrict__ attn_b,
                             const float* __restrict__ comb_W,
                             const float* __restrict__ comb_b,
                             float* __restrict__ attnw_out) {
    __shared__ __align__(16) float s_in[2 * H];   // [emb ; h0]
    __shared__ __align__(16) float s_cx[2 * H];   // [emb ; applied]
    __shared__ float s_logit[L];
    __shared__ float s_w[L];
    const int tid = threadIdx.x;
    const int w = tid >> 5, lane = tid & 31;
    pdl_trigger();

    if (blockIdx.x == 0 && tid == 0) g_sum = 0.f;  // reset for this replay

    const int idx = input[0];     // low 32 bits of LE int64 index
    const float* e = emb + (size_t)idx * H;
    for (int i = tid; i < H; i += 256) {
        float v = e[i];
        s_in[i] = v;
        s_cx[i] = v;
        s_in[H + i] = h_hidden[i];
    }
    __syncthreads();

    const float4* s_in4 = (const float4*)s_in;
    for (int l = w; l < L; l += 8) {
        const float4* row = (const float4*)(attn_W + (size_t)l * 2 * H);
        float acc = 0.f;
#pragma unroll
        for (int t = 0; t < 16; t++) {
            float4 a = row[lane + 32 * t];
            float4 b = s_in4[lane + 32 * t];
            acc += a.x * b.x + a.y * b.y + a.z * b.z + a.w * b.w;
        }
        acc = warp_sum(acc);
        if (lane == 0) s_logit[l] = acc + attn_b[l];
    }
    __syncthreads();

    if (tid == 0) {
        float m = -1e30f;
#pragma unroll
        for (int l = 0; l < L; l++) m = fmaxf(m, s_logit[l]);
        float s = 0.f;
#pragma unroll
        for (int l = 0; l < L; l++) { float ex = expf(s_logit[l] - m); s_w[l] = ex; s += ex; }
        float inv = 1.f / s;
#pragma unroll
        for (int l = 0; l < L; l++) s_w[l] *= inv;
        if (blockIdx.x == 0)
#pragma unroll
            for (int l = 0; l < L; l++) attnw_out[l] = s_w[l];
    }
    __syncthreads();

    for (int j = tid; j < H; j += 256) {
        float acc = 0.f;
#pragma unroll
        for (int l = 0; l < L; l++) acc += s_w[l] * enc[l * H + j];
        s_cx[H + j] = acc;
    }
    __syncthreads();

    const int r = blockIdx.x * 8 + w;
    const float4* s_cx4 = (const float4*)s_cx;
    const float4* row = (const float4*)(comb_W + (size_t)r * 2 * H);
    float acc = 0.f;
#pragma unroll
    for (int t = 0; t < 16; t++) {
        float4 a = ldcs4(row + lane + 32 * t);
        float4 b = s_cx4[lane + 32 * t];
        acc += a.x * b.x + a.y * b.y + a.z * b.z + a.w * b.w;
    }
    acc = warp_sum(acc);
    if (lane == 0) g_x[r] = fmaxf(acc + comb_b[r], 0.f);
}

// ============================================================
// Kernel 2: full LSTM (hh + ih gates + cell). 512 blocks x 256.
// Warp w handles (unit u = w>>2, gate g = w&3) for units 2b,2b+1.
// PRE-WAIT: hh dot (depends only on h_hidden) + W_ih L2 prefetch
//   — overlaps with k1's attention/combine.
// POST-WAIT: ih dot (needs g_x), gate sum, cell math in-block.
// ============================================================
__global__ void __launch_bounds__(256, 6)
k2_lstm(const float* __restrict__ h_hidden,
        const float* __restrict__ c_hidden,
        const float* __restrict__ W_ih,
        const float* __restrict__ W_hh,
        const float* __restrict__ b_ih,
        const float* __restrict__ b_hh,
        float* __restrict__ h_new,
        float* __restrict__ c_new) {
    __shared__ __align__(16) float4 s_h[256];     // h0
    __shared__ __align__(16) float4 s_x[256];     // g_x (post-wait)
    __shared__ float s_gate[8];                   // [unit][gate]
    const int tid = threadIdx.x;
    const int w = tid >> 5, lane = tid & 31;
    const int u = w >> 2;                 // 0..1 local unit
    const int g = w & 3;                  // gate index
    const int j = blockIdx.x * 2 + u;     // hidden unit
    const int r = g * H + j;              // gate row
    pdl_trigger();

    // ---- pre-wait: hh dot + prefetch ih row ----
    s_h[tid] = ((const float4*)h_hidden)[tid];
    {
        const char* ih_base = (const char*)(W_ih + (size_t)r * H);
        l2_prefetch(ih_base + lane * 128);       // 32 x 128B = 4KB row
    }
    __syncthreads();

    const float4* hrow = (const float4*)(W_hh + (size_t)r * H);
    float acc_hh = 0.f;
#pragma unroll
    for (int t = 0; t < 8; t++) {
        float4 a = ldcs4(hrow + lane + 32 * t);
        float4 b = s_h[lane + 32 * t];
        acc_hh += a.x * b.x + a.y * b.y + a.z * b.z + a.w * b.w;
    }

    // ---- wait for k1's g_x ----
    pdl_wait();
    s_x[tid] = ((const float4*)g_x)[tid];
    __syncthreads();

    const float4* irow = (const float4*)(W_ih + (size_t)r * H);
    float acc_ih = 0.f;
#pragma unroll
    for (int t = 0; t < 8; t++) {
        float4 a = ldcs4(irow + lane + 32 * t);
        float4 b = s_x[lane + 32 * t];
        acc_ih += a.x * b.x + a.y * b.y + a.z * b.z + a.w * b.w;
    }
    float gate = warp_sum(acc_ih + acc_hh);
    if (lane == 0) s_gate[u * 4 + g] = gate + b_ih[r] + b_hh[r];
    __syncthreads();

    if (tid < 2) {
        const int jj = blockIdx.x * 2 + tid;
        float gi = s_gate[tid * 4 + 0];
        float gf = s_gate[tid * 4 + 1];
        float gg = s_gate[tid * 4 + 2];
        float go = s_gate[tid * 4 + 3];
        float si = 1.f / (1.f + expf(-gi));
        float sf = 1.f / (1.f + expf(-gf));
        float so = 1.f / (1.f + expf(-go));
        float c = sf * c_hidden[jj] + si * tanhf(gg);
        float h = so * tanhf(c);
        c_new[jj] = c;
        h_new[jj] = h;
        g_h[jj] = h;
    }
}

// ============================================================
// Kernel 3: output projection, 8 rows/block, warp-per-row.
// PDL consumer: prefetches its 32KB out_W tile into L2 BEFORE
// waiting. Epilogue: fire-and-forget REDG into g_sum.
// ============================================================
__global__ void k3_out(const float* __restrict__ out_W,
                       const float* __restrict__ out_b,
                       float* __restrict__ logits) {
    __shared__ __align__(16) float4 s_h[256];
    __shared__ float s_l[8];
    const int tid = threadIdx.x;
    const int w = tid >> 5, lane = tid & 31;
    const int r = blockIdx.x * 8 + w;
    pdl_trigger();

    if (r < V) {
        const char* base = (const char*)(out_W + (size_t)r * H);
        l2_prefetch(base + lane * 128);  // 32 lanes cover the 4KB row
    }

    pdl_wait();                          // k2's g_h now visible
    s_h[tid] = ((const float4*)g_h)[tid];
    __syncthreads();

    float l = -CUDART_INF_F;
    if (r < V) {
        const float4* row = (const float4*)(out_W + (size_t)r * H);
        float acc = 0.f;
#pragma unroll
        for (int t = 0; t < 8; t++) {
            float4 a = ldcs4(row + lane + 32 * t);
            float4 b = s_h[lane + 32 * t];
            acc += a.x * b.x + a.y * b.y + a.z * b.z + a.w * b.w;
        }
        acc = warp_sum(acc);
        if (lane == 0) {
            l = acc + out_b[r];
            logits[r] = l;
        }
    }
    if (lane == 0) s_l[w] = l;
    __syncthreads();
    if (tid == 0) {
        float s = 0.f;
#pragma unroll
        for (int i = 0; i < 8; i++) {
            float v = s_l[i];
            if (v != -CUDART_INF_F) s += expf(v);
        }
        atomicAdd(&g_sum, s);            // REDG: no return value, no fence
    }
}

// ============================================================
// Kernel 4: logp[i] = logits[i] - log(g_sum). PDL consumer.
// ============================================================
__global__ void k4_sub(float* __restrict__ logp) {
    __shared__ float s_lse;
    const int tid = threadIdx.x;
    pdl_wait();
    if (tid == 0) s_lse = logf(g_sum);
    __syncthreads();
    const float lse = s_lse;
    const int i = blockIdx.x * 256 + tid;
    if (i < V) logp[i] -= lse;
}

// ============================================================
static inline void launch_pdl(void* fn, dim3 grid, dim3 block, void** args) {
    cudaLaunchAttribute attr[1];
    attr[0].id = cudaLaunchAttributeProgrammaticStreamSerialization;
    attr[0].val.programmaticStreamSerializationAllowed = 1;
    cudaLaunchConfig_t cfg = {};
    cfg.gridDim = grid;
    cfg.blockDim = block;
    cfg.dynamicSmemBytes = 0;
    cfg.stream = 0;
    cfg.attrs = attr;
    cfg.numAttrs = 1;
    cudaLaunchKernelExC(&cfg, fn, args);
}

extern "C" void kernel_launch(void* const* d_in, const int* in_sizes, int n_in,
                              void* d_out, int out_size) {
    const int*   input   = (const int*)  d_in[0];
    const float* h_hid   = (const float*)d_in[1];
    const float* c_hid   = (const float*)d_in[2];
    const float* enc     = (const float*)d_in[3];
    const float* emb     = (const float*)d_in[4];
    const float* attn_W  = (const float*)d_in[5];
    const float* attn_b  = (const float*)d_in[6];
    const float* comb_W  = (const float*)d_in[7];
    const float* comb_b  = (const float*)d_in[8];
    const float* W_ih    = (const float*)d_in[9];
    const float* W_hh    = (const float*)d_in[10];
    const float* b_ih    = (const float*)d_in[11];
    const float* b_hh    = (const float*)d_in[12];
    const float* out_W   = (const float*)d_in[13];
    const float* out_b   = (const float*)d_in[14];

    float* out   = (float*)d_out;
    float* logp  = out;                 // [V]
    float* h_new = out + V;             // [H]
    float* c_new = out + V + H;         // [H]
    float* attnw = out + V + 2 * H;     // [L]

    k1_attn_comb<<<128, 256>>>(input, h_hid, enc, emb, attn_W, attn_b,
                               comb_W, comb_b, attnw);
    {
        void* args[] = { (void*)&h_hid, (void*)&c_hid, (void*)&W_ih, (void*)&W_hh,
                         (void*)&b_ih, (void*)&b_hh, (void*)&h_new, (void*)&c_new };
        launch_pdl((void*)k2_lstm, dim3(512), dim3(256), args);
    }
    {
        void* args[] = { (void*)&out_W, (void*)&out_b, (void*)&logp };
        launch_pdl((void*)k3_out, dim3(TILES), dim3(256), args);
    }
    {
        void* args[] = { (void*)&logp };
        launch_pdl((void*)k4_sub, dim3((V + 255) / 256), dim3(256), args);
    }
}